// round 13
// baseline (speedup 1.0000x reference)
#include <cuda_runtime.h>

// Simulate_22497038696790 — batched dual-phase RK4 RSV model.
// R13 = R12 (scalar head / packed mid / scalar tail, NSUB=3, 1 warp/SMSP)
// with branchless u-substitution in the SCALAR sections:
//   U = (beta*dt)*V ; per tau = t/dt:
//     T' = -U*T ; E' = U*T - (delta*dt)E ; U' = (bd*p*dt)E - (c*dt)U
//   => q = U*T is ONE mul (was two): 37 ops/step vs 41. Constants folded
//   unconditionally each segment (no compare/branch — the R11 killer);
//   V recovered once per segment via rcp.approx + FSEL (dt==0-safe: steps
//   are exact identities, select keeps old V, the 0*inf NaN is discarded).
// Packed mid keeps the V-form (needs exact identity on its dt==0 lane).
// Also: incremental 32-bit store offsets (no per-segment 64-bit IMADs).
// Output: [2, 4, 17, B] f32, index = ((phase*4 + comp)*17 + seg)*B + b

#define NSUB 3
#define NT 17
#define BLOCK 128

typedef unsigned long long u64;

static __device__ __forceinline__ u64 pk(float lo, float hi) {
    u64 r; asm("mov.b64 %0, {%1, %2};" : "=l"(r) : "f"(lo), "f"(hi)); return r;
}
static __device__ __forceinline__ void upk(u64 v, float &lo, float &hi) {
    asm("mov.b64 {%0, %1}, %2;" : "=f"(lo), "=f"(hi) : "l"(v));
}
static __device__ __forceinline__ u64 f2fma(u64 a, u64 b, u64 c) {
    u64 d; asm("fma.rn.f32x2 %0, %1, %2, %3;" : "=l"(d) : "l"(a), "l"(b), "l"(c)); return d;
}
static __device__ __forceinline__ u64 f2mul(u64 a, u64 b) {
    u64 d; asm("mul.rn.f32x2 %0, %1, %2;" : "=l"(d) : "l"(a), "l"(b)); return d;
}
static __device__ __forceinline__ u64 f2add(u64 a, u64 b) {
    u64 d; asm("add.rn.f32x2 %0, %1, %2;" : "=l"(d) : "l"(a), "l"(b)); return d;
}
static __device__ __forceinline__ float frcp(float x) {
    float r; asm("rcp.approx.f32 %0, %1;" : "=f"(r) : "f"(x)); return r;
}

// -------- scalar RK4 on (T, E, U): 37 ops, distributed accumulation --------
static __device__ __forceinline__ void rk4u(float &T, float &E, float &U,
                                            float ndd, float bpd, float ncd)
{
    const float H = 0.5f, S = 1.0f / 6.0f, TH = 1.0f / 3.0f;
    float q1 = U * T;
    float e1 = fmaf(ndd, E, q1);
    float u1 = fmaf(bpd, E, ncd * U);
    float Ta = fmaf(-S, q1, T), Ea = fmaf(S, e1, E), Ua = fmaf(S, u1, U);
    float Tm = fmaf(-H, q1, T), Em = fmaf(H, e1, E), Um = fmaf(H, u1, U);
    float q2 = Um * Tm;
    float e2 = fmaf(ndd, Em, q2);
    float u2 = fmaf(bpd, Em, ncd * Um);
    Ta = fmaf(-TH, q2, Ta); Ea = fmaf(TH, e2, Ea); Ua = fmaf(TH, u2, Ua);
    Tm = fmaf(-H, q2, T);  Em = fmaf(H, e2, E);  Um = fmaf(H, u2, U);
    float q3 = Um * Tm;
    float e3 = fmaf(ndd, Em, q3);
    float u3 = fmaf(bpd, Em, ncd * Um);
    Ta = fmaf(-TH, q3, Ta); Ea = fmaf(TH, e3, Ea); Ua = fmaf(TH, u3, Ua);
    Tm = T - q3; Em = E + e3; Um = U + u3;
    float q4 = Um * Tm;
    float e4 = fmaf(ndd, Em, q4);
    float u4 = fmaf(bpd, Em, ncd * Um);
    T = fmaf(-S, q4, Ta); E = fmaf(S, e4, Ea); U = fmaf(S, u4, Ua);
}

// One scalar segment in u-space; branchless, dt==0-safe.
static __device__ __forceinline__ void seg_u(
    float &T, float &E, float &V, float dt,
    float beta, float delta, float p, float c)
{
    float bd    = beta * dt;
    float ndd   = -delta * dt;
    float ncd   = -c * dt;
    float bpd   = bd * (p * dt);
    float invbd = frcp(bd);                 // MUFU, off the serial chain
    float U     = bd * V;
#pragma unroll
    for (int k = 0; k < NSUB; ++k) rk4u(T, E, U, ndd, bpd, ncd);
    float Vn = U * invbd;                   // NaN when dt==0; discarded below
    V = (dt != 0.0f) ? Vn : V;              // FSEL, no branch
}

// ---------------- packed RK4 (R12 form; dt==0 lane => exact identity) ------
struct K2 { u64 half, nhalf, sixth, nsixth, third, nthird; };

static __device__ __forceinline__ void seg_packed(
    u64 &T, u64 &E, u64 &V, float dtA, float dtB,
    u64 b2, u64 nd2, u64 p2, u64 nc2, const K2 &kc)
{
    const u64 dt2 = pk(dtA, dtB);
    const u64 bd  = f2mul(b2, dt2);
    const u64 ndd = f2mul(nd2, dt2);
    const u64 pd  = f2mul(p2, dt2);
    const u64 ncd = f2mul(nc2, dt2);

#pragma unroll
    for (int k = 0; k < NSUB; ++k) {
        u64 q1 = f2mul(f2mul(bd, V), T);
        u64 e1 = f2fma(ndd, E, q1);
        u64 v1 = f2fma(pd, E, f2mul(ncd, V));
        u64 Ta = f2fma(kc.nsixth, q1, T);
        u64 Ea = f2fma(kc.sixth, e1, E);
        u64 Va = f2fma(kc.sixth, v1, V);
        u64 Tm = f2fma(kc.nhalf, q1, T);
        u64 Em = f2fma(kc.half, e1, E);
        u64 Vm = f2fma(kc.half, v1, V);
        u64 q2 = f2mul(f2mul(bd, Vm), Tm);
        u64 e2 = f2fma(ndd, Em, q2);
        u64 v2 = f2fma(pd, Em, f2mul(ncd, Vm));
        Ta = f2fma(kc.nthird, q2, Ta);
        Ea = f2fma(kc.third, e2, Ea);
        Va = f2fma(kc.third, v2, Va);
        Tm = f2fma(kc.nhalf, q2, T);
        Em = f2fma(kc.half, e2, E);
        Vm = f2fma(kc.half, v2, V);
        u64 q3 = f2mul(f2mul(bd, Vm), Tm);
        u64 e3 = f2fma(ndd, Em, q3);
        u64 v3 = f2fma(pd, Em, f2mul(ncd, Vm));
        Ta = f2fma(kc.nthird, q3, Ta);
        Ea = f2fma(kc.third, e3, Ea);
        Va = f2fma(kc.third, v3, Va);
        Tm = f2fma(pk(-1.0f, -1.0f), q3, T);
        Em = f2add(E, e3);
        Vm = f2add(V, v3);
        u64 q4 = f2mul(f2mul(bd, Vm), Tm);
        u64 e4 = f2fma(ndd, Em, q4);
        u64 v4 = f2fma(pd, Em, f2mul(ncd, Vm));
        T = f2fma(kc.nsixth, q4, Ta);
        E = f2fma(kc.sixth, e4, Ea);
        V = f2fma(kc.sixth, v4, Va);
    }
}

__global__ __launch_bounds__(BLOCK)
void Simulate_22497038696790_kernel(
    const float* __restrict__ days1, const float* __restrict__ days2,
    const float* __restrict__ D0,   const float* __restrict__ E0,
    const float* __restrict__ V01,  const float* __restrict__ V02,
    const float* __restrict__ beta_, const float* __restrict__ delta_,
    const float* __restrict__ p_,    const float* __restrict__ c_,
    const int* __restrict__ treatment,
    float* __restrict__ out, int B)
{
    int b = blockIdx.x * BLOCK + threadIdx.x;
    if (b >= B) return;

    const float beta  = beta_[b];
    const float delta = delta_[b];
    const float p     = p_[b];
    const float c     = c_[b];
    const int   treat = treatment[0];

    float d1[NT], d2[NT];
#pragma unroll
    for (int i = 0; i < NT; i++) { d1[i] = __ldg(days1 + i); d2[i] = __ldg(days2 + i); }

    // first index where days1 == 15.0 (jnp.argmax semantics: 0 if none)
    int idx15 = 0;
#pragma unroll
    for (int i = NT - 1; i >= 0; i--) if (d1[i] == 15.0f) idx15 = i;

    const unsigned uB = (unsigned)B;
    const unsigned S1 = (unsigned)NT * uB;       // component stride
    const unsigned S2 = 2u * S1, S3 = 3u * S1;
    float* const o = out + b;                    // thread base pointer

    // ---- Section 1: HEAD, scalar u-form, phase-1 segments 0..idx15 ----
    float E1 = E0[b];
    float T1 = 1.0f - D0[b] - E1;
    float V1 = treat ? V01[b] : 0.0f;

    float t = 5.0f;
    unsigned off = 0;                            // = s * uB, incremental
    for (int s = 0; s <= idx15; ++s) {
        float tn = d1[s];
        seg_u(T1, E1, V1, (tn - t) * (1.0f / NSUB), beta, delta, p, c);
        t = tn;
        o[off]      = 1.0f - T1 - E1;            // phase 0
        o[off + S1] = E1;
        o[off + S2] = V1;
        o[off + S3] = __logf(V1);
        off += uB;
    }

    // ---- Day-15 restart ----
    float T2 = T1, E2 = E1;
    float V2 = treat ? (V1 + V02[b]) : V1;

    // ---- Section 2: MID, packed; lane0 = phase-1 rem, lane1 = phase-2 ----
    const u64 b2  = pk(beta, beta);
    const u64 nd2 = pk(-delta, -delta);
    const u64 p2  = pk(p, p);
    const u64 nc2 = pk(-c, -c);
    K2 kc;
    kc.half   = pk(0.5f, 0.5f);
    kc.nhalf  = pk(-0.5f, -0.5f);
    kc.sixth  = pk(1.0f / 6.0f, 1.0f / 6.0f);
    kc.nsixth = pk(-1.0f / 6.0f, -1.0f / 6.0f);
    kc.third  = pk(1.0f / 3.0f, 1.0f / 3.0f);
    kc.nthird = pk(-1.0f / 3.0f, -1.0f / 3.0f);

    int n1rem = NT - 1 - idx15;                  // paired segment count

    u64 T = pk(T1, T2), E = pk(E1, E2), V = pk(V1, V2);
    float tA = t, tB = 15.0f;
    int   sA = idx15 + 1;
    int   s2 = 0;
    unsigned off2 = 4u * S1;                     // phase-1 block offset
    for (; s2 < n1rem; ++s2) {
        float tnA = d1[sA];
        float dtA = (tnA - tA) * (1.0f / NSUB);
        float tnB = d2[s2];
        float dtB = (tnB - tB) * (1.0f / NSUB);

        seg_packed(T, E, V, dtA, dtB, b2, nd2, p2, nc2, kc);

        float Tl, Th, El, Eh, Vl, Vh;
        upk(T, Tl, Th); upk(E, El, Eh); upk(V, Vl, Vh);
        o[off]       = 1.0f - Tl - El;           // phase 0, seg sA
        o[off + S1]  = El;
        o[off + S2]  = Vl;
        o[off + S3]  = __logf(Vl);
        o[off2]      = 1.0f - Th - Eh;           // phase 1, seg s2
        o[off2 + S1] = Eh;
        o[off2 + S2] = Vh;
        o[off2 + S3] = __logf(Vh);

        off += uB; off2 += uB;
        tA = tnA; ++sA;
        tB = tnB;
    }

    // ---- Section 3: END, scalar u-form, phase-2 segments n1rem..NT-1 ----
    {
        float Tl, Th, El, Eh, Vl, Vh;
        upk(T, Tl, Th); upk(E, El, Eh); upk(V, Vl, Vh);
        T2 = Th; E2 = Eh; V2 = Vh;
    }
    for (; s2 < NT; ++s2) {
        float tnB = d2[s2];
        seg_u(T2, E2, V2, (tnB - tB) * (1.0f / NSUB), beta, delta, p, c);
        tB = tnB;
        o[off2]      = 1.0f - T2 - E2;           // phase 1
        o[off2 + S1] = E2;
        o[off2 + S2] = V2;
        o[off2 + S3] = __logf(V2);
        off2 += uB;
    }
}

extern "C" void kernel_launch(void* const* d_in, const int* in_sizes, int n_in,
                              void* d_out, int out_size)
{
    const float* days1 = (const float*)d_in[0];
    const float* days2 = (const float*)d_in[1];
    const float* D0    = (const float*)d_in[2];
    const float* E0    = (const float*)d_in[3];
    const float* V01   = (const float*)d_in[4];
    const float* V02   = (const float*)d_in[5];
    const float* beta  = (const float*)d_in[6];
    const float* delta = (const float*)d_in[7];
    const float* p     = (const float*)d_in[8];
    const float* c     = (const float*)d_in[9];
    const int*   treat = (const int*)d_in[10];

    int B = in_sizes[2];
    int grid = (B + BLOCK - 1) / BLOCK;
    Simulate_22497038696790_kernel<<<grid, BLOCK>>>(
        days1, days2, D0, E0, V01, V02, beta, delta, p, c, treat,
        (float*)d_out, B);
}